// round 17
// baseline (speedup 1.0000x reference)
#include <cuda_runtime.h>
#include <cuda_fp16.h>
#include <cstdint>

#define NN 100000
#define EE 3200000
#define SCAN_B 512
#define NBLK_SCAN ((NN + SCAN_B - 1) / SCAN_B)

// -------- device scratch (no cudaMalloc allowed) --------
__device__ __half g_pxh[NN * 128];       // fp16 dis-prescaled x
__device__ __half g_yh[NN * 128];        // y = A_hat x (fp16)
__device__ __half g_ph[3][NN * 128];     // per-scale dis*LN(relu(...)) fp16
__device__ __half g_th[3][NN * 128];     // per-scale t_s (fp16)
__device__ __half g_pzh[NN * 64];        // fp16 tail (summed, dis-scaled)
__device__ float  g_wc[384 * 64];
__device__ __half g_w0h[3 * 128 * 128];
__device__ __half g_w1h[3 * 128 * 128];
__device__ __half g_wch[384 * 64], g_wcl[384 * 64];
__device__ float  g_cbias[64];
__device__ float  g_dis[NN];
__device__ int    g_deg[NN];
__device__ int    g_rowptr[NN];
__device__ int    g_rpcopy[NN];
__device__ int    g_col[EE];
__device__ int    g_bsum[NBLK_SCAN + 1];

// ---------------------------------------------------------------------------
// graph prep
// ---------------------------------------------------------------------------
__global__ void zero_kernel(int* deg, int n) {
    int i = blockIdx.x * blockDim.x + threadIdx.x;
    if (i < n) deg[i] = 0;
}

__global__ void count_kernel(const int* __restrict__ dst, int* __restrict__ deg, int e) {
    int i = (blockIdx.x * blockDim.x + threadIdx.x) * 2;
    if (i + 1 < e) {
        int2 d = *(const int2*)(dst + i);
        atomicAdd(&deg[d.x], 1);
        atomicAdd(&deg[d.y], 1);
    } else if (i < e) {
        atomicAdd(&deg[dst[i]], 1);
    }
}

__global__ void scan1_kernel(const int* __restrict__ deg, int* __restrict__ out,
                             int* __restrict__ bsum, float* __restrict__ dis, int n) {
    __shared__ int sh[SCAN_B];
    int tid = threadIdx.x;
    int i = blockIdx.x * SCAN_B + tid;
    int v = (i < n) ? deg[i] : 0;
    if (i < n) dis[i] = rsqrtf((float)v + 1.0f);
    sh[tid] = v;
    __syncthreads();
#pragma unroll
    for (int off = 1; off < SCAN_B; off <<= 1) {
        int t = (tid >= off) ? sh[tid - off] : 0;
        __syncthreads();
        sh[tid] += t;
        __syncthreads();
    }
    if (i < n) out[i] = sh[tid] - v;
    if (tid == SCAN_B - 1) bsum[blockIdx.x] = sh[tid];
}

__global__ void scan2_kernel(int* bsum, int nb) {
    if (threadIdx.x == 0 && blockIdx.x == 0) {
        int acc = 0;
        for (int i = 0; i < nb; i++) { int t = bsum[i]; bsum[i] = acc; acc += t; }
    }
}

__global__ void scan3_kernel(int* __restrict__ out, int* __restrict__ rpcopy,
                             const int* __restrict__ bsum, int n) {
    int i = blockIdx.x * blockDim.x + threadIdx.x;
    if (i < n) {
        int v = out[i] + bsum[i / SCAN_B];
        out[i] = v;
        rpcopy[i] = v;
    }
}

__global__ void fill_kernel(const int* __restrict__ src, const int* __restrict__ dst,
                            int* __restrict__ rpcopy, int* __restrict__ col, int e) {
    int i = (blockIdx.x * blockDim.x + threadIdx.x) * 2;
    if (i + 1 < e) {
        int2 d = *(const int2*)(dst + i);
        int2 s = *(const int2*)(src + i);
        col[atomicAdd(&rpcopy[d.x], 1)] = s.x;
        col[atomicAdd(&rpcopy[d.y], 1)] = s.y;
    } else if (i < e) {
        col[atomicAdd(&rpcopy[dst[i]], 1)] = src[i];
    }
}

// ---------------------------------------------------------------------------
// weight folding / conversion / prescale
// ---------------------------------------------------------------------------
__global__ void wc_kernel(const float* __restrict__ W2, const float* __restrict__ Wf,
                          float* __restrict__ Wc) {
    int r = blockIdx.x;
    int s = r >> 7, i = r & 127;
    int j = threadIdx.x;
    float acc = 0.0f;
#pragma unroll 8
    for (int k = 0; k < 64; k++)
        acc = fmaf(W2[(s * 128 + i) * 64 + k], Wf[(s * 64 + k) * 64 + j], acc);
    Wc[r * 64 + j] = acc;
}

__global__ void cbias_kernel(const float* __restrict__ b2, const float* __restrict__ Wf,
                             const float* __restrict__ bf, float* __restrict__ cb) {
    int j = threadIdx.x;
    float acc = bf[j];
#pragma unroll 8
    for (int r = 0; r < 192; r++) acc = fmaf(b2[r], Wf[r * 64 + j], acc);
    cb[j] = acc;
}

__global__ void convs_kernel(const float* __restrict__ W, __half* __restrict__ Wh, int n) {
    int i = blockIdx.x * blockDim.x + threadIdx.x;
    if (i < n) Wh[i] = __float2half_rn(W[i]);
}

__global__ void convh_kernel(const float* __restrict__ W, __half* __restrict__ Wh,
                             __half* __restrict__ Wl, int n) {
    int i = blockIdx.x * blockDim.x + threadIdx.x;
    if (i < n) {
        float w = W[i];
        __half h = __float2half_rn(w);
        Wh[i] = h;
        Wl[i] = __float2half_rn(w - __half2float(h));
    }
}

__global__ void prescale_h_kernel(const float4* __restrict__ x, const float* __restrict__ dis,
                                  uint2* __restrict__ px, int n4) {
    int i = blockIdx.x * blockDim.x + threadIdx.x;
    if (i < n4) {
        float s = dis[i >> 5];
        float4 v = x[i];
        __half2 h0 = __floats2half2_rn(v.x * s, v.y * s);
        __half2 h1 = __floats2half2_rn(v.z * s, v.w * s);
        uint2 u;
        u.x = *(uint32_t*)&h0; u.y = *(uint32_t*)&h1;
        px[i] = u;
    }
}

// ---------------------------------------------------------------------------
// PTX helpers
// ---------------------------------------------------------------------------
__device__ __forceinline__ uint32_t smem_u32(const void* p) {
    uint32_t a;
    asm("{ .reg .u64 t; cvta.to.shared.u64 t, %1; cvt.u32.u64 %0, t; }"
        : "=r"(a) : "l"(p));
    return a;
}

#define LDSM_X4(r, addr)                                                      \
    asm volatile("ldmatrix.sync.aligned.m8n8.x4.shared.b16 {%0,%1,%2,%3}, [%4];" \
                 : "=r"((r)[0]), "=r"((r)[1]), "=r"((r)[2]), "=r"((r)[3])     \
                 : "r"(addr))

#define LDSM_X2T(r, addr)                                                     \
    asm volatile("ldmatrix.sync.aligned.m8n8.x2.trans.shared.b16 {%0,%1}, [%2];" \
                 : "=r"((r)[0]), "=r"((r)[1]) : "r"(addr))

#define MMA_F16(d, a, b)                                                      \
    asm volatile("mma.sync.aligned.m16n8k16.row.col.f32.f16.f16.f32 "         \
                 "{%0,%1,%2,%3}, {%4,%5,%6,%7}, {%8,%9}, {%0,%1,%2,%3};"      \
                 : "+f"((d)[0]), "+f"((d)[1]), "+f"((d)[2]), "+f"((d)[3])     \
                 : "r"((a)[0]), "r"((a)[1]), "r"((a)[2]), "r"((a)[3]),        \
                   "r"((b)[0]), "r"((b)[1]))

// ---------------------------------------------------------------------------
// merged GEMM0: per 128-row tile, loop 3 scales:
//   ph_s = dis * LN(relu(yh @ W0h_s + b0_s))   (fp16 out)
// ---------------------------------------------------------------------------
__global__ void __launch_bounds__(256)
gemm0m_kernel(const __half* __restrict__ A, const __half* __restrict__ w0h_all,
              const float* __restrict__ dis, const float* __restrict__ b0,
              const float* __restrict__ gamma, const float* __restrict__ beta,
              __half* __restrict__ ph_all, int rbase, int nrows) {
    constexpr int LDA = 136, LDB = 136;
    constexpr int WN = 4, WM = 2, WROWS = 64, MI = 4, NJ = 4;
    constexpr int ABYTES = 128 * LDA * 2;
    extern __shared__ char smem[];
    __shared__ float sh_bias[3][128], sh_g[3][128], sh_b[3][128];

    int tid = threadIdx.x, wid = tid >> 5, lane = tid & 31;
    int warp_m = wid % WM, warp_n = wid / WM;
    int m0 = rbase + blockIdx.x * 128;
    uint32_t sb = smem_u32(smem);

    if (tid < 128) {
#pragma unroll
        for (int s = 0; s < 3; s++) {
            sh_bias[s][tid] = b0[s * 128 + tid];
            sh_g[s][tid] = gamma[(s * 3 + 0) * 128 + tid];
            sh_b[s][tid] = beta[(s * 3 + 0) * 128 + tid];
        }
    }

    int a_r = lane & 15, a_c8 = (lane >> 4) * 8, b_r = lane & 15;
    int g = lane >> 2, q2 = (lane & 3) * 2;
    int row = tid >> 1, half = tid & 1;
    int rg = m0 + row;
    float sc = (rg < nrows) ? dis[rg] : 0.0f;

    for (int s = 0; s < 3; s++) {
        if (s) __syncthreads();   // prior epilogue reads done before re-staging
        // stage A (from L2-hot yh) + W0_s
#pragma unroll
        for (int it = 0; it < 8; it++) {
            int idx = it * 256 + tid;
            int r = idx >> 4, u4 = idx & 15;
            int rr = m0 + r;
            uint4 v = make_uint4(0u, 0u, 0u, 0u);
            if (rr < nrows) v = *(const uint4*)(A + (size_t)rr * 128 + u4 * 8);
            *(uint4*)(smem + (r * LDA + u4 * 8) * 2) = v;
            *(uint4*)(smem + ABYTES + (r * LDB + u4 * 8) * 2) =
                *(const uint4*)(w0h_all + s * 16384 + r * 128 + u4 * 8);
        }
        __syncthreads();

        float acc[MI][NJ][4];
#pragma unroll
        for (int i = 0; i < MI; i++)
#pragma unroll
            for (int j = 0; j < NJ; j++)
#pragma unroll
                for (int k = 0; k < 4; k++) acc[i][j][k] = 0.0f;

#pragma unroll
        for (int ks = 0; ks < 8; ks++) {
            uint32_t af[MI][4], bf_[NJ][2];
#pragma unroll
            for (int mi = 0; mi < MI; mi++)
                LDSM_X4(af[mi], sb + ((warp_m * WROWS + mi * 16 + a_r) * LDA
                                      + ks * 16 + a_c8) * 2);
#pragma unroll
            for (int nj = 0; nj < NJ; nj++)
                LDSM_X2T(bf_[nj], sb + ABYTES + ((ks * 16 + b_r) * LDB
                                                 + warp_n * 32 + nj * 8) * 2);
#pragma unroll
            for (int mi = 0; mi < MI; mi++)
#pragma unroll
                for (int nj = 0; nj < NJ; nj++)
                    MMA_F16(acc[mi][nj], af[mi], bf_[nj]);
        }

        __syncthreads();
        float* Cs = (float*)smem;   // [128][129], overwrites A|W (re-staged next s)
#pragma unroll
        for (int mi = 0; mi < MI; mi++)
#pragma unroll
            for (int nj = 0; nj < NJ; nj++) {
                int rl = warp_m * WROWS + mi * 16 + g;
                int c = warp_n * 32 + nj * 8 + q2;
                Cs[rl * 129 + c]           = acc[mi][nj][0];
                Cs[rl * 129 + c + 1]       = acc[mi][nj][1];
                Cs[(rl + 8) * 129 + c]     = acc[mi][nj][2];
                Cs[(rl + 8) * 129 + c + 1] = acc[mi][nj][3];
            }
        __syncthreads();

        float v[64];
        float s1 = 0.0f, s2 = 0.0f;
#pragma unroll
        for (int j = 0; j < 64; j++) {
            float t = fmaxf(Cs[row * 129 + half * 64 + j] + sh_bias[s][half * 64 + j], 0.0f);
            v[j] = t; s1 += t; s2 += t * t;
        }
        s1 += __shfl_xor_sync(0xffffffffu, s1, 1);
        s2 += __shfl_xor_sync(0xffffffffu, s2, 1);
        float mu = s1 * (1.0f / 128.0f);
        float var = s2 * (1.0f / 128.0f) - mu * mu;
        float inv = rsqrtf(var + 1e-5f);

        if (rg < nrows) {
            __half* outp = ph_all + (size_t)s * NN * 128 + (size_t)rg * 128 + half * 64;
#pragma unroll
            for (int j = 0; j < 64; j += 8) {
                float o[8];
#pragma unroll
                for (int q = 0; q < 8; q++)
                    o[q] = ((v[j + q] - mu) * inv * sh_g[s][half * 64 + j + q]
                            + sh_b[s][half * 64 + j + q]) * sc;
                __half2 h0 = __floats2half2_rn(o[0], o[1]);
                __half2 h1 = __floats2half2_rn(o[2], o[3]);
                __half2 h2 = __floats2half2_rn(o[4], o[5]);
                __half2 h3 = __floats2half2_rn(o[6], o[7]);
                uint4 u;
                u.x = *(uint32_t*)&h0; u.y = *(uint32_t*)&h1;
                u.z = *(uint32_t*)&h2; u.w = *(uint32_t*)&h3;
                *(uint4*)(outp + j) = u;
            }
        }
    }
}

// ---------------------------------------------------------------------------
// merged GEMM1 + folded tail over 3 scales:
//   u_s = LN(relu(t_s @ W1_s + b1_s));  pz += u_s @ Wc_s (hi/lo)
//   pzh = fp16(pz * dis[row])
// ---------------------------------------------------------------------------
__global__ void __launch_bounds__(256)
gemm1fm_kernel(const __half* __restrict__ th_all, const __half* __restrict__ w1h_all,
               const __half* __restrict__ wch_all, const __half* __restrict__ wcl_all,
               const float* __restrict__ b1, const float* __restrict__ gamma,
               const float* __restrict__ beta, const float* __restrict__ dis,
               __half* __restrict__ pzh, int nrows) {
    constexpr int LDA = 136, LDB = 136, LDC = 72;
    constexpr int WN = 4, WM = 2, WROWS = 64, MI = 4, NJ = 4;
    constexpr int ABYTES = 128 * LDA * 2;
    constexpr int UOFF = 0, CH = 34816, CL = 34816 + 18432;
    extern __shared__ char smem[];
    __shared__ float sh_bias[3][128], sh_g[3][128], sh_b[3][128];

    int tid = threadIdx.x, wid = tid >> 5, lane = tid & 31;
    int warp_m = wid % WM, warp_n = wid / WM;
    int m0 = blockIdx.x * 128;
    uint32_t sb = smem_u32(smem);

    if (tid < 128) {
#pragma unroll
        for (int s = 0; s < 3; s++) {
            sh_bias[s][tid] = b1[s * 128 + tid];
            sh_g[s][tid] = gamma[(s * 3 + 1) * 128 + tid];
            sh_b[s][tid] = beta[(s * 3 + 1) * 128 + tid];
        }
    }

    int a_r = lane & 15, a_c8 = (lane >> 4) * 8, b_r = lane & 15;
    int g = lane >> 2, q2 = (lane & 3) * 2;
    int row = tid >> 1, half = tid & 1;
    int warp_m2 = wid & 3, warp_n2 = wid >> 2;

    float acc2[2][4][4];
#pragma unroll
    for (int i = 0; i < 2; i++)
#pragma unroll
        for (int j = 0; j < 4; j++)
#pragma unroll
            for (int k = 0; k < 4; k++) acc2[i][j][k] = 0.0f;

    for (int s = 0; s < 3; s++) {
        if (s) __syncthreads();
        const __half* A = th_all + (size_t)s * NN * 128;
#pragma unroll
        for (int it = 0; it < 8; it++) {
            int idx = it * 256 + tid;
            int r = idx >> 4, u4 = idx & 15;
            int rr = m0 + r;
            uint4 v = make_uint4(0u, 0u, 0u, 0u);
            if (rr < nrows) v = *(const uint4*)(A + (size_t)rr * 128 + u4 * 8);
            *(uint4*)(smem + (r * LDA + u4 * 8) * 2) = v;
            *(uint4*)(smem + ABYTES + (r * LDB + u4 * 8) * 2) =
                *(const uint4*)(w1h_all + s * 16384 + r * 128 + u4 * 8);
        }
        __syncthreads();

        float acc[MI][NJ][4];
#pragma unroll
        for (int i = 0; i < MI; i++)
#pragma unroll
            for (int j = 0; j < NJ; j++)
#pragma unroll
                for (int k = 0; k < 4; k++) acc[i][j][k] = 0.0f;

#pragma unroll
        for (int ks = 0; ks < 8; ks++) {
            uint32_t af[MI][4], bf_[NJ][2];
#pragma unroll
            for (int mi = 0; mi < MI; mi++)
                LDSM_X4(af[mi], sb + ((warp_m * WROWS + mi * 16 + a_r) * LDA
                                      + ks * 16 + a_c8) * 2);
#pragma unroll
            for (int nj = 0; nj < NJ; nj++)
                LDSM_X2T(bf_[nj], sb + ABYTES + ((ks * 16 + b_r) * LDB
                                                 + warp_n * 32 + nj * 8) * 2);
#pragma unroll
            for (int mi = 0; mi < MI; mi++)
#pragma unroll
                for (int nj = 0; nj < NJ; nj++)
                    MMA_F16(acc[mi][nj], af[mi], bf_[nj]);
        }

        __syncthreads();
        float* Cs = (float*)smem;
#pragma unroll
        for (int mi = 0; mi < MI; mi++)
#pragma unroll
            for (int nj = 0; nj < NJ; nj++) {
                int rl = warp_m * WROWS + mi * 16 + g;
                int c = warp_n * 32 + nj * 8 + q2;
                Cs[rl * 129 + c]           = acc[mi][nj][0];
                Cs[rl * 129 + c + 1]       = acc[mi][nj][1];
                Cs[(rl + 8) * 129 + c]     = acc[mi][nj][2];
                Cs[(rl + 8) * 129 + c + 1] = acc[mi][nj][3];
            }
        __syncthreads();

        float v[64];
        float s1 = 0.0f, s2 = 0.0f;
#pragma unroll
        for (int j = 0; j < 64; j++) {
            float t = fmaxf(Cs[row * 129 + half * 64 + j] + sh_bias[s][half * 64 + j], 0.0f);
            v[j] = t; s1 += t; s2 += t * t;
        }
        s1 += __shfl_xor_sync(0xffffffffu, s1, 1);
        s2 += __shfl_xor_sync(0xffffffffu, s2, 1);
        float mu = s1 * (1.0f / 128.0f);
        float var = s2 * (1.0f / 128.0f) - mu * mu;
        float inv = rsqrtf(var + 1e-5f);

        __syncthreads();   // all Cs reads done before u overwrites smem

        {
            __half* uP = (__half*)(smem + UOFF);
#pragma unroll
            for (int j = 0; j < 64; j += 8) {
                float o[8];
#pragma unroll
                for (int q = 0; q < 8; q++)
                    o[q] = (v[j + q] - mu) * inv * sh_g[s][half * 64 + j + q]
                           + sh_b[s][half * 64 + j + q];
                __half2 h0 = __floats2half2_rn(o[0], o[1]);
                __half2 h1 = __floats2half2_rn(o[2], o[3]);
                __half2 h2 = __floats2half2_rn(o[4], o[5]);
                __half2 h3 = __floats2half2_rn(o[6], o[7]);
                uint4 u;
                u.x = *(uint32_t*)&h0; u.y = *(uint32_t*)&h1;
                u.z = *(uint32_t*)&h2; u.w = *(uint32_t*)&h3;
                *(uint4*)(uP + row * LDA + half * 64 + j) = u;
            }
        }
#pragma unroll
        for (int it = 0; it < 4; it++) {
            int idx = it * 256 + tid;
            int kk = idx >> 3, u4 = idx & 7;
            *(uint4*)(smem + CH + (kk * LDC + u4 * 8) * 2) =
                *(const uint4*)(wch_all + s * 8192 + kk * 64 + u4 * 8);
            *(uint4*)(smem + CL + (kk * LDC + u4 * 8) * 2) =
                *(const uint4*)(wcl_all + s * 8192 + kk * 64 + u4 * 8);
        }
        __syncthreads();

#pragma unroll
        for (int p = 0; p < 2; p++) {
            uint32_t bB = sb + (p ? CL : CH);
#pragma unroll
            for (int ks = 0; ks < 8; ks++) {
                uint32_t af[2][4], bf_[4][2];
#pragma unroll
                for (int mi = 0; mi < 2; mi++)
                    LDSM_X4(af[mi], sb + UOFF + ((warp_m2 * 32 + mi * 16 + a_r) * LDA
                                                 + ks * 16 + a_c8) * 2);
#pragma unroll
                for (int nj = 0; nj < 4; nj++)
                    LDSM_X2T(bf_[nj], bB + ((ks * 16 + b_r) * LDC
                                            + warp_n2 * 32 + nj * 8) * 2);
#pragma unroll
                for (int mi = 0; mi < 2; mi++)
#pragma unroll
                    for (int nj = 0; nj < 4; nj++)
                        MMA_F16(acc2[mi][nj], af[mi], bf_[nj]);
            }
        }
    }

    // final: pzh = fp16(acc2 * dis[row])
#pragma unroll
    for (int mi = 0; mi < 2; mi++)
#pragma unroll
        for (int nj = 0; nj < 4; nj++) {
            int c = warp_n2 * 32 + nj * 8 + q2;
            int r0 = m0 + warp_m2 * 32 + mi * 16 + g;
            if (r0 < nrows) {
                float sd = dis[r0];
                __half2 h = __floats2half2_rn(acc2[mi][nj][0] * sd, acc2[mi][nj][1] * sd);
                *(uint32_t*)(pzh + (size_t)r0 * 64 + c) = *(uint32_t*)&h;
            }
            int r1 = r0 + 8;
            if (r1 < nrows) {
                float sd = dis[r1];
                __half2 h = __floats2half2_rn(acc2[mi][nj][2] * sd, acc2[mi][nj][3] * sd);
                *(uint32_t*)(pzh + (size_t)r1 * 64 + c) = *(uint32_t*)&h;
            }
        }
}

#define SMEM_G0 (34816 * 2)
#define SMEM_G1F 71680

// ---------------------------------------------------------------------------
// single-buffer aggregation (warp per node), fp16 in/out, 32-bit offsets
// ---------------------------------------------------------------------------
__global__ void __launch_bounds__(256)
agg128hh_kernel(const __half* __restrict__ p, const float* __restrict__ dis,
                const int* __restrict__ rowptr, const int* __restrict__ deg,
                const int* __restrict__ col, __half* __restrict__ out,
                int base, int nend) {
    int w = base + ((blockIdx.x * blockDim.x + threadIdx.x) >> 5);
    if (w >= nend) return;
    int lane = threadIdx.x & 31;
    const uint2* p2 = (const uint2*)p;
    int start = rowptr[w], d = deg[w];
    uint2 a = p2[(uint32_t)w * 32u + lane];
    float2 f0 = __half22float2(*(__half2*)&a.x);
    float2 f1 = __half22float2(*(__half2*)&a.y);
    float ax = f0.x, ay = f0.y, az = f1.x, aw = f1.y;

    int c0 = 0;
    for (; c0 + 32 <= d; c0 += 32) {
        int idx = col[start + c0 + lane];
#pragma unroll 16
        for (int j = 0; j < 32; j++) {
            uint32_t u = (uint32_t)__shfl_sync(0xffffffffu, idx, j);
            uint2 v = p2[u * 32u + lane];
            float2 g0 = __half22float2(*(__half2*)&v.x);
            float2 g1 = __half22float2(*(__half2*)&v.y);
            ax += g0.x; ay += g0.y; az += g1.x; aw += g1.y;
        }
    }
    int m = d - c0;
    if (m > 0) {
        int idx = (lane < m) ? col[start + c0 + lane] : 0;
        for (int j = 0; j < m; j++) {
            uint32_t u = (uint32_t)__shfl_sync(0xffffffffu, idx, j);
            uint2 v = p2[u * 32u + lane];
            float2 g0 = __half22float2(*(__half2*)&v.x);
            float2 g1 = __half22float2(*(__half2*)&v.y);
            ax += g0.x; ay += g0.y; az += g1.x; aw += g1.y;
        }
    }
    float s = dis[w];
    __half2 h0 = __floats2half2_rn(ax * s, ay * s);
    __half2 h1 = __floats2half2_rn(az * s, aw * s);
    uint2 o;
    o.x = *(uint32_t*)&h0; o.y = *(uint32_t*)&h1;
    ((uint2*)out)[(uint32_t)w * 32u + lane] = o;
}

// merged 3-scale mid aggregation: one col pass, 3x uint2 gathers per index
__global__ void __launch_bounds__(256)
agg384h_kernel(const __half* __restrict__ ph0, const float* __restrict__ dis,
               const int* __restrict__ rowptr, const int* __restrict__ deg,
               const int* __restrict__ col, __half* __restrict__ th0, int n) {
    int w = (blockIdx.x * blockDim.x + threadIdx.x) >> 5;
    if (w >= n) return;
    int lane = threadIdx.x & 31;
    const uint2* q0 = (const uint2*)ph0;
    const uint2* q1 = q0 + (size_t)NN * 32;
    const uint2* q2 = q1 + (size_t)NN * 32;
    int start = rowptr[w], d = deg[w];

    float acc[12];
    {
        uint32_t soff = (uint32_t)w * 32u + lane;
        uint2 a0 = q0[soff], a1 = q1[soff], a2 = q2[soff];
        float2 f;
        f = __half22float2(*(__half2*)&a0.x); acc[0] = f.x;  acc[1] = f.y;
        f = __half22float2(*(__half2*)&a0.y); acc[2] = f.x;  acc[3] = f.y;
        f = __half22float2(*(__half2*)&a1.x); acc[4] = f.x;  acc[5] = f.y;
        f = __half22float2(*(__half2*)&a1.y); acc[6] = f.x;  acc[7] = f.y;
        f = __half22float2(*(__half2*)&a2.x); acc[8] = f.x;  acc[9] = f.y;
        f = __half22float2(*(__half2*)&a2.y); acc[10] = f.x; acc[11] = f.y;
    }

    int c0 = 0;
    for (; c0 + 32 <= d; c0 += 32) {
        int idx = col[start + c0 + lane];
#pragma unroll 8
        for (int j = 0; j < 32; j++) {
            uint32_t u = (uint32_t)__shfl_sync(0xffffffffu, idx, j);
            uint32_t off = u * 32u + lane;
            uint2 v0 = q0[off], v1 = q1[off], v2 = q2[off];
            float2 f;
            f = __half22float2(*(__half2*)&v0.x); acc[0] += f.x;  acc[1] += f.y;
            f = __half22float2(*(__half2*)&v0.y); acc[2] += f.x;  acc[3] += f.y;
            f = __half22float2(*(__half2*)&v1.x); acc[4] += f.x;  acc[5] += f.y;
            f = __half22float2(*(__half2*)&v1.y); acc[6] += f.x;  acc[7] += f.y;
            f = __half22float2(*(__half2*)&v2.x); acc[8] += f.x;  acc[9] += f.y;
            f = __half22float2(*(__half2*)&v2.y); acc[10] += f.x; acc[11] += f.y;
        }
    }
    int m = d - c0;
    if (m > 0) {
        int idx = (lane < m) ? col[start + c0 + lane] : 0;
        for (int j = 0; j < m; j++) {
            uint32_t u = (uint32_t)__shfl_sync(0xffffffffu, idx, j);
            uint32_t off = u * 32u + lane;
            uint2 v0 = q0[off], v1 = q1[off], v2 = q2[off];
            float2 f;
            f = __half22float2(*(__half2*)&v0.x); acc[0] += f.x;  acc[1] += f.y;
            f = __half22float2(*(__half2*)&v0.y); acc[2] += f.x;  acc[3] += f.y;
            f = __half22float2(*(__half2*)&v1.x); acc[4] += f.x;  acc[5] += f.y;
            f = __half22float2(*(__half2*)&v1.y); acc[6] += f.x;  acc[7] += f.y;
            f = __half22float2(*(__half2*)&v2.x); acc[8] += f.x;  acc[9] += f.y;
            f = __half22float2(*(__half2*)&v2.y); acc[10] += f.x; acc[11] += f.y;
        }
    }

    float s = dis[w];
    uint2* t0 = (uint2*)th0;
    uint2* t1 = t0 + (size_t)NN * 32;
    uint2* t2 = t1 + (size_t)NN * 32;
    uint32_t ooff = (uint32_t)w * 32u + lane;
    uint2 o;
    __half2 h0, h1;
    h0 = __floats2half2_rn(acc[0] * s, acc[1] * s);
    h1 = __floats2half2_rn(acc[2] * s, acc[3] * s);
    o.x = *(uint32_t*)&h0; o.y = *(uint32_t*)&h1;
    __stcs(t0 + ooff, o);
    h0 = __floats2half2_rn(acc[4] * s, acc[5] * s);
    h1 = __floats2half2_rn(acc[6] * s, acc[7] * s);
    o.x = *(uint32_t*)&h0; o.y = *(uint32_t*)&h1;
    __stcs(t1 + ooff, o);
    h0 = __floats2half2_rn(acc[8] * s, acc[9] * s);
    h1 = __floats2half2_rn(acc[10] * s, acc[11] * s);
    o.x = *(uint32_t*)&h0; o.y = *(uint32_t*)&h1;
    __stcs(t2 + ooff, o);
}

// fp16 payload, 64-wide rows: final output fp32 + cbias
__global__ void __launch_bounds__(256)
agg64h_kernel(const uint32_t* __restrict__ p, const float* __restrict__ dis,
              const int* __restrict__ rowptr, const int* __restrict__ deg,
              const int* __restrict__ col, const float* __restrict__ cbias,
              float2* __restrict__ out, int n) {
    int w = (blockIdx.x * blockDim.x + threadIdx.x) >> 5;
    if (w >= n) return;
    int lane = threadIdx.x & 31;
    int start = rowptr[w], d = deg[w];
    uint32_t a = p[(uint32_t)w * 32u + lane];
    float2 f = __half22float2(*(__half2*)&a);
    float ax = f.x, ay = f.y;

    int c0 = 0;
    for (; c0 + 32 <= d; c0 += 32) {
        int idx = col[start + c0 + lane];
#pragma unroll 16
        for (int j = 0; j < 32; j++) {
            uint32_t u = (uint32_t)__shfl_sync(0xffffffffu, idx, j);
            uint32_t v = p[u * 32u + lane];
            float2 g = __half22float2(*(__half2*)&v);
            ax += g.x; ay += g.y;
        }
    }
    int m = d - c0;
    if (m > 0) {
        int idx = (lane < m) ? col[start + c0 + lane] : 0;
        for (int j = 0; j < m; j++) {
            uint32_t u = (uint32_t)__shfl_sync(0xffffffffu, idx, j);
            uint32_t v = p[u * 32u + lane];
            float2 g = __half22float2(*(__half2*)&v);
            ax += g.x; ay += g.y;
        }
    }
    float s = dis[w];
    float2 o = {ax * s + cbias[lane * 2], ay * s + cbias[lane * 2 + 1]};
    out[(uint32_t)w * 32u + lane] = o;
}

// ---------------------------------------------------------------------------
extern "C" void kernel_launch(void* const* d_in, const int* in_sizes, int n_in,
                              void* d_out, int out_size) {
    const float* x     = (const float*)d_in[0];
    const int*   ei    = (const int*)d_in[1];
    const float* W0    = (const float*)d_in[2];
    const float* b0    = (const float*)d_in[3];
    const float* W1    = (const float*)d_in[4];
    const float* b1    = (const float*)d_in[5];
    const float* W2    = (const float*)d_in[6];
    const float* b2    = (const float*)d_in[7];
    const float* gamma = (const float*)d_in[8];
    const float* beta  = (const float*)d_in[9];
    const float* Wf    = (const float*)d_in[10];
    const float* bf    = (const float*)d_in[11];
    float* out = (float*)d_out;

    const int N = in_sizes[0] / 128;
    const int E = in_sizes[1] / 2;
    const int* src = ei;
    const int* dst = ei + E;

    __half *pxh, *yh, *ph, *th, *pzh, *w0h, *w1h, *wch, *wcl;
    float *wc, *cbias, *dis;
    int *deg, *rp, *rpc, *col, *bsum;
    cudaGetSymbolAddress((void**)&pxh,   g_pxh);
    cudaGetSymbolAddress((void**)&yh,    g_yh);
    cudaGetSymbolAddress((void**)&ph,    g_ph);
    cudaGetSymbolAddress((void**)&th,    g_th);
    cudaGetSymbolAddress((void**)&pzh,   g_pzh);
    cudaGetSymbolAddress((void**)&wc,    g_wc);
    cudaGetSymbolAddress((void**)&w0h,   g_w0h);
    cudaGetSymbolAddress((void**)&w1h,   g_w1h);
    cudaGetSymbolAddress((void**)&wch,   g_wch);
    cudaGetSymbolAddress((void**)&wcl,   g_wcl);
    cudaGetSymbolAddress((void**)&cbias, g_cbias);
    cudaGetSymbolAddress((void**)&dis,   g_dis);
    cudaGetSymbolAddress((void**)&deg,   g_deg);
    cudaGetSymbolAddress((void**)&rp,    g_rowptr);
    cudaGetSymbolAddress((void**)&rpc,   g_rpcopy);
    cudaGetSymbolAddress((void**)&col,   g_col);
    cudaGetSymbolAddress((void**)&bsum,  g_bsum);

    // 2 created streams + legacy default, 6 events (guard-safe envelope)
    static bool inited = false;
    static cudaStream_t st1, st2;
    static cudaEvent_t evRoot, evDis, evPre, evW, evY0, ev1;
    if (!inited) {
        cudaStreamCreateWithFlags(&st1, cudaStreamNonBlocking);
        cudaStreamCreateWithFlags(&st2, cudaStreamNonBlocking);
        cudaEventCreateWithFlags(&evRoot, cudaEventDisableTiming);
        cudaEventCreateWithFlags(&evDis, cudaEventDisableTiming);
        cudaEventCreateWithFlags(&evPre, cudaEventDisableTiming);
        cudaEventCreateWithFlags(&evW,  cudaEventDisableTiming);
        cudaEventCreateWithFlags(&evY0, cudaEventDisableTiming);
        cudaEventCreateWithFlags(&ev1,  cudaEventDisableTiming);
        cudaFuncSetAttribute(gemm0m_kernel,
                             cudaFuncAttributeMaxDynamicSharedMemorySize, SMEM_G0);
        cudaFuncSetAttribute(gemm1fm_kernel,
                             cudaFuncAttributeMaxDynamicSharedMemorySize, SMEM_G1F);
        inited = true;
    }

    const int TB = 256;
    int nB = (N + TB - 1) / TB;
    int e2B = (E / 2 + TB - 1) / TB + 1;
    int nbScan = (N + SCAN_B - 1) / SCAN_B;
    int aggB = (N * 32 + TB - 1) / TB;
    int gB = (N + 127) / 128;

    const int H = ((N / 2 + 127) / 128) * 128;
    int gB0 = H / 128;
    int gB1 = (N - H + 127) / 128;
    int aB0 = (H * 32 + TB - 1) / TB;
    int aB1 = ((N - H) * 32 + TB - 1) / TB;

    cudaStream_t s0 = 0;

    // --- capture fork for st1 (weights) ---
    zero_kernel<<<nB, TB, 0, s0>>>(deg, N);
    cudaEventRecord(evRoot, s0);
    cudaStreamWaitEvent(st1, evRoot, 0);

    // --- weight folding + fp16 conversion on st1 ---
    wc_kernel<<<384, 64, 0, st1>>>(W2, Wf, wc);
    cbias_kernel<<<1, 64, 0, st1>>>(b2, Wf, bf, cbias);
    convs_kernel<<<(3 * 128 * 128 + 255) / 256, 256, 0, st1>>>(W0, w0h, 3 * 128 * 128);
    convs_kernel<<<(3 * 128 * 128 + 255) / 256, 256, 0, st1>>>(W1, w1h, 3 * 128 * 128);
    convh_kernel<<<(384 * 64 + 255) / 256, 256, 0, st1>>>(wc, wch, wcl, 384 * 64);
    cudaEventRecord(evW, st1);

    // --- graph prep on s0 ---
    count_kernel<<<e2B, TB, 0, s0>>>(dst, deg, E);
    scan1_kernel<<<nbScan, SCAN_B, 0, s0>>>(deg, rp, bsum, dis, N);
    cudaEventRecord(evDis, s0);

    cudaStreamWaitEvent(st2, evDis, 0);
    prescale_h_kernel<<<(N * 32 + TB - 1) / TB, TB, 0, st2>>>(
        (const float4*)x, dis, (uint2*)pxh, N * 32);
    cudaEventRecord(evPre, st2);

    scan2_kernel<<<1, 32, 0, s0>>>(bsum, nbScan);
    scan3_kernel<<<nB, TB, 0, s0>>>(rp, rpc, bsum, N);
    fill_kernel<<<e2B, TB, 0, s0>>>(src, dst, rpc, col, E);

    // --- agg_y in halves; merged GEMM0 H0 on st1 overlaps agg_y H1 on s0 ---
    cudaStreamWaitEvent(s0, evPre, 0);
    agg128hh_kernel<<<aB0, TB, 0, s0>>>(pxh, dis, rp, deg, col, yh, 0, H);
    cudaEventRecord(evY0, s0);
    agg128hh_kernel<<<aB1, TB, 0, s0>>>(pxh, dis, rp, deg, col, yh, H, N);

    cudaStreamWaitEvent(st1, evY0, 0);
    gemm0m_kernel<<<gB0, 256, SMEM_G0, st1>>>(
        yh, w0h, dis, b0, gamma, beta, ph, 0, N);
    cudaEventRecord(ev1, st1);

    cudaStreamWaitEvent(s0, evW, 0);
    gemm0m_kernel<<<gB1, 256, SMEM_G0, s0>>>(
        yh, w0h, dis, b0, gamma, beta, ph, H, N);
    cudaStreamWaitEvent(s0, ev1, 0);

    // --- merged 3-scale mid aggregation ---
    agg384h_kernel<<<aggB, TB, 0, s0>>>(ph, dis, rp, deg, col, th, N);

    // --- merged GEMM1 + folded tail (pz accumulated in registers) ---
    gemm1fm_kernel<<<gB, 256, SMEM_G1F, s0>>>(
        th, w1h, wch, wcl, b1, gamma, beta, dis, pzh, N);

    // --- final aggregation ---
    agg64h_kernel<<<aggB, TB, 0, s0>>>((const uint32_t*)pzh, dis, rp, deg, col,
                                       cbias, (float2*)out, N);
}